// round 5
// baseline (speedup 1.0000x reference)
#include <cuda_runtime.h>
#include <cstdint>

#define THREADS 128
#define ROWS_PER_THREAD 2
#define ROWS_PER_BLOCK (THREADS * ROWS_PER_THREAD)   // 256

// --- packed f32x2 FMA: two rn-FMAs, one issue slot ---
#define FMA2(d, a, b) asm("fma.rn.f32x2 %0, %1, %2, %0;" : "+l"(d) : "l"(a), "l"(b))
#define PACK2(d, s)   asm("mov.b64 %0, {%1, %1};" : "=l"(d) : "r"(s))
#define UNPACK2(lo, hi, d) asm("mov.b64 {%0, %1}, %2;" : "=r"(lo), "=r"(hi) : "l"(d))

// --- fast transcendentals on the MUFU pipe ---
__device__ __forceinline__ float softplus_fast(float x) {
    float e, l;
    float y = fabsf(x) * -1.4426950408889634f;
    asm("ex2.approx.f32 %0, %1;" : "=f"(e) : "f"(y));
    float u = 1.0f + e;
    asm("lg2.approx.f32 %0, %1;" : "=f"(l) : "f"(u));
    return fmaxf(x, 0.0f) + l * 0.6931471805599453f;
}
__device__ __forceinline__ float exp_fast(float x) {
    float e;
    asm("ex2.approx.f32 %0, %1;" : "=f"(e) : "f"(x * 1.4426950408889634f));
    return e;
}
__device__ __forceinline__ float rcp_fast(float x) {
    float r;
    asm("rcp.approx.f32 %0, %1;" : "=f"(r) : "f"(x));
    return r;
}

// SMEM layout (floats):
//   [0, 9216)     Ws (16x24x24)
//   [9216, 9288)  W_out
//   [9288, 9291)  b_out
//   [9296, ...)   x staging: 256 rows x 27
#define SM_WS    0
#define SM_WOUT  9216
#define SM_BOUT  9288
#define SM_X     9296
#define SM_FLOATS (SM_X + ROWS_PER_BLOCK * 27)

__device__ __forceinline__ void epilogue_row(
    const float* __restrict__ xr, const float* __restrict__ S,
    const float* __restrict__ sWout, const float* __restrict__ sbout,
    float bt, float bc, float a1, float a2, float a3,
    float* __restrict__ op)
{
    float u[24];
    #pragma unroll
    for (int j = 0; j < 19; j++) u[j] = xr[j] - S[j];
    u[19] = xr[21] - S[19];
    u[20] = xr[24] - S[20];
    u[21] = fmaf(bc, xr[20], fmaf(bt, xr[19], a1)) - S[21];
    u[22] = fmaf(bc, xr[23], fmaf(bt, xr[22], a2)) - S[22];
    u[23] = fmaf(bc, xr[26], fmaf(bt, xr[25], a3)) - S[23];

    float m = u[0];
    #pragma unroll
    for (int j = 1; j < 24; j++) m = fmaxf(m, u[j]);

    float e[24];
    float sum = 0.0f;
    #pragma unroll
    for (int j = 0; j < 24; j++) { e[j] = exp_fast(u[j] - m); sum += e[j]; }
    const float inv = rcp_fast(sum);

    float d0 = 0.0f, d1 = 0.0f, d2 = 0.0f;
    #pragma unroll
    for (int j = 0; j < 24; j++) {
        const float ej = e[j];
        d0 = fmaf(ej, sWout[j * 3 + 0], d0);
        d1 = fmaf(ej, sWout[j * 3 + 1], d1);
        d2 = fmaf(ej, sWout[j * 3 + 2], d2);
    }
    op[0] = fmaxf(fmaf(d0, inv, sbout[0]), 0.0f);
    op[1] = fmaxf(fmaf(d1, inv, sbout[1]), 0.0f);
    op[2] = fmaxf(fmaf(d2, inv, sbout[2]), 0.0f);
}

__global__ __launch_bounds__(THREADS, 3)
void reslogit_kernel(const float* __restrict__ x,
                     const float* __restrict__ asc_train,
                     const float* __restrict__ asc_sm,
                     const float* __restrict__ asc_car,
                     const float* __restrict__ b_time,
                     const float* __restrict__ b_cost,
                     const float* __restrict__ Ws,
                     const float* __restrict__ W_out,
                     const float* __restrict__ b_out,
                     float* __restrict__ out,
                     int B)
{
    extern __shared__ float smem[];
    float* sW    = smem + SM_WS;
    float* sWout = smem + SM_WOUT;
    float* sbout = smem + SM_BOUT;
    float* sx    = smem + SM_X;

    const int tid  = threadIdx.x;
    const int row0 = blockIdx.x * ROWS_PER_BLOCK;

    // cooperative load of Ws as float4 (2304 float4; 2304 % 128 == 0 -> 18 iters)
    {
        const float4* Ws4 = reinterpret_cast<const float4*>(Ws);
        float4* sW4 = reinterpret_cast<float4*>(sW);
        #pragma unroll
        for (int i = 0; i < 2304 / THREADS; i++)
            sW4[tid + i * THREADS] = Ws4[tid + i * THREADS];
    }
    if (tid < 72) sWout[tid] = W_out[tid];
    if (tid < 3)  sbout[tid] = b_out[tid];

    // cooperative, coalesced load of this block's x rows (256 x 27)
    {
        const float* xblk = x + (size_t)row0 * 27;
        int nrow  = B - row0; if (nrow > ROWS_PER_BLOCK) nrow = ROWS_PER_BLOCK;
        int nelem = nrow * 27;
        for (int i = tid; i < nelem; i += THREADS) sx[i] = xblk[i];
    }
    __syncthreads();

    const int rowA = row0 + tid;
    const int rowB = rowA + THREADS;
    const bool hasA = rowA < B, hasB = rowB < B;
    if (!hasA) return;

    const float bt = *b_time, bc = *b_cost;
    const float a1 = *asc_train, a2 = *asc_sm, a3 = *asc_car;

    const float* xrA = sx + tid * 27;              // stride 27: conflict-free
    const float* xrB = sx + (tid + THREADS) * 27;

    float ovA[24], ovB[24], SA[24], SB[24];
    #pragma unroll
    for (int j = 0; j < 19; j++) { ovA[j] = xrA[j]; ovB[j] = xrB[j]; }
    ovA[19] = xrA[21]; ovB[19] = xrB[21];
    ovA[20] = xrA[24]; ovB[20] = xrB[24];
    ovA[21] = fmaf(bc, xrA[20], fmaf(bt, xrA[19], a1));
    ovB[21] = fmaf(bc, xrB[20], fmaf(bt, xrB[19], a1));
    ovA[22] = fmaf(bc, xrA[23], fmaf(bt, xrA[22], a2));
    ovB[22] = fmaf(bc, xrB[23], fmaf(bt, xrB[22], a2));
    ovA[23] = fmaf(bc, xrA[26], fmaf(bt, xrA[25], a3));
    ovB[23] = fmaf(bc, xrB[26], fmaf(bt, xrB[25], a3));
    #pragma unroll
    for (int j = 0; j < 24; j++) { SA[j] = 0.0f; SB[j] = 0.0f; }

    // 16-step scan. j-dimension split into two halves of 12 to cap register
    // pressure (acc = 6 packed pairs per row). Each W element still loaded
    // exactly once per thread (serves both rows via FFMA2 + row reuse).
    #pragma unroll 1
    for (int k = 0; k < 16; k++) {
        const float* Wk = sW + k * 576;

        #pragma unroll
        for (int h = 0; h < 2; h++) {
            uint64_t accA[6], accB[6];
            #pragma unroll
            for (int p = 0; p < 6; p++) { accA[p] = 0ull; accB[p] = 0ull; }

            #pragma unroll
            for (int i = 0; i < 24; i++) {
                // 12 floats = 3x LDS.128; 16B-aligned (i*24*4 + h*48 bytes)
                const double2* Wr = reinterpret_cast<const double2*>(Wk + i * 24 + h * 12);
                const double2 w0 = Wr[0];
                const double2 w1 = Wr[1];
                const double2 w2 = Wr[2];
                uint64_t wp[6];
                wp[0] = *reinterpret_cast<const uint64_t*>(&w0.x);
                wp[1] = *reinterpret_cast<const uint64_t*>(&w0.y);
                wp[2] = *reinterpret_cast<const uint64_t*>(&w1.x);
                wp[3] = *reinterpret_cast<const uint64_t*>(&w1.y);
                wp[4] = *reinterpret_cast<const uint64_t*>(&w2.x);
                wp[5] = *reinterpret_cast<const uint64_t*>(&w2.y);

                uint64_t ooA, ooB;
                PACK2(ooA, __float_as_uint(ovA[i]));
                PACK2(ooB, __float_as_uint(ovB[i]));

                #pragma unroll
                for (int p = 0; p < 6; p++) {
                    FMA2(accA[p], ooA, wp[p]);
                    FMA2(accB[p], ooB, wp[p]);
                }
            }

            // softplus + scan update for this half's 12 columns
            #pragma unroll
            for (int p = 0; p < 6; p++) {
                const int j0 = h * 12 + 2 * p;
                uint32_t lo, hi;
                UNPACK2(lo, hi, accA[p]);
                SA[j0]     += softplus_fast(__uint_as_float(lo));
                SA[j0 + 1] += softplus_fast(__uint_as_float(hi));
                UNPACK2(lo, hi, accB[p]);
                SB[j0]     += softplus_fast(__uint_as_float(lo));
                SB[j0 + 1] += softplus_fast(__uint_as_float(hi));
            }
        }

        // ov_k = ov_{k-1} - S_k (running sum)
        #pragma unroll
        for (int j = 0; j < 24; j++) {
            ovA[j] -= SA[j];
            ovB[j] -= SB[j];
        }
    }

    epilogue_row(xrA, SA, sWout, sbout, bt, bc, a1, a2, a3, out + (size_t)rowA * 3);
    if (hasB)
        epilogue_row(xrB, SB, sWout, sbout, bt, bc, a1, a2, a3, out + (size_t)rowB * 3);
}

extern "C" void kernel_launch(void* const* d_in, const int* in_sizes, int n_in,
                              void* d_out, int out_size)
{
    const float* x         = (const float*)d_in[0];
    const float* asc_train = (const float*)d_in[1];
    const float* asc_sm    = (const float*)d_in[2];
    const float* asc_car   = (const float*)d_in[3];
    const float* b_time    = (const float*)d_in[4];
    const float* b_cost    = (const float*)d_in[5];
    const float* Ws        = (const float*)d_in[6];
    const float* W_out     = (const float*)d_in[7];
    const float* b_out     = (const float*)d_in[8];
    float* out = (float*)d_out;

    const int B = in_sizes[0] / 27;
    const int smem_bytes = SM_FLOATS * sizeof(float);

    cudaFuncSetAttribute(reslogit_kernel,
                         cudaFuncAttributeMaxDynamicSharedMemorySize, smem_bytes);

    const int grid = (B + ROWS_PER_BLOCK - 1) / ROWS_PER_BLOCK;
    reslogit_kernel<<<grid, THREADS, smem_bytes>>>(
        x, asc_train, asc_sm, asc_car, b_time, b_cost, Ws, W_out, b_out, out, B);
}